// round 1
// baseline (speedup 1.0000x reference)
#include <cuda_runtime.h>
#include <math.h>

// ---------------------------------------------------------------------------
// MS-SSIM + L1 loss, fully fused separable-Gaussian implementation.
//
// Pipeline:
//   initCoefs : extract 5 x 33 1-D Gaussian kernels from g_masks diag (g = sqrt(diag))
//   hconv     : horizontal 1-D conv of 6 derived fields (x, y, x^2, y^2, xy, |x-y|)
//               per (batch, channel) for the sigmas that channel needs.
//               38 planes per batch -> scratch. Also block-partials of raw |x-y|.
//   vkern     : vertical 1-D conv (register-blocked) + SSIM pointwise + block
//               partial sums of loss_mix.
//   mseK      : (disc_out - 1)^2 sum.
//   finalK    : deterministic final combine -> scalar.
// ---------------------------------------------------------------------------

#define SCR_PLANE 262144               // 512*512
#define PLANES_PER_B 38

__device__ float g_scr[8 * PLANES_PER_B * SCR_PLANE];  // ~304 MB scratch
__device__ float g_g1d[5 * 33];
__device__ float g_partL1[24576];
__device__ float g_partLoss[1024];
__device__ float g_mse[1];

#define C1c 1.0e-4f
#define C2c 9.0e-4f

// ---------------------------------------------------------------------------
__global__ void initCoefs(const float* __restrict__ gm) {
    int t = threadIdx.x;
    if (t < 165) {
        int s = t / 33, i = t % 33;
        // 2D mask = outer(g, g); diag[i] = g[i]^2, g >= 0.
        g_g1d[t] = sqrtf(fmaxf(gm[(3 * s) * 1089 + i * 34], 0.0f));
    }
}

// ---------------------------------------------------------------------------
__device__ __forceinline__ float blockReduce256(float v) {
    __shared__ float r[256];
    int tid = threadIdx.x;
    r[tid] = v;
    __syncthreads();
#pragma unroll
    for (int s = 128; s > 0; s >>= 1) {
        if (tid < s) r[tid] += r[tid + s];
        __syncthreads();
    }
    float out = r[0];
    __syncthreads();
    return out;
}

// ---------------------------------------------------------------------------
// Horizontal pass worker, specialized per input channel C.
// Sigma sets:  C=0 -> {s0(r3), s1(r6)}  planes {0,5}
//              C=1 -> {s1(r6), s2(r11), s3(r16)} planes {10,15,20}
//              C=2 -> {s3(r16), s4(r16)} planes {25,30}
// L1 field always convolved with s4 (r16), plane 35+C.
template <int C>
__device__ __forceinline__ void hwork(const float* sf, int tid, size_t obase) {
    constexpr int S0 = (C == 0) ? 0 : (C == 1) ? 1 : 3;
    constexpr int S1 = (C == 0) ? 1 : (C == 1) ? 2 : 4;
    constexpr int S2 = 3;  // only C==1
    constexpr int R0 = (C == 0) ? 3 : (C == 1) ? 6 : 16;
    constexpr int R1 = (C == 0) ? 6 : (C == 1) ? 11 : 16;
    constexpr int P0 = (C == 0) ? 0 : (C == 1) ? 10 : 25;
    constexpr int P1 = (C == 0) ? 5 : (C == 1) ? 15 : 30;
    constexpr int P2 = 20;

    float a0[5] = {0, 0, 0, 0, 0};
    float a1[5] = {0, 0, 0, 0, 0};
    float a2[5] = {0, 0, 0, 0, 0};
    float aL = 0.0f;

#pragma unroll
    for (int j = 0; j < 33; j++) {
        float f0 = sf[0 * 288 + tid + j];
        float f1 = sf[1 * 288 + tid + j];
        float f2 = sf[2 * 288 + tid + j];
        float f3 = sf[3 * 288 + tid + j];
        float f4 = sf[4 * 288 + tid + j];
        float f5 = sf[5 * 288 + tid + j];

        float gl = g_g1d[4 * 33 + j];
        aL = fmaf(gl, f5, aL);

        if (j >= 16 - R0 && j <= 16 + R0) {
            float g = g_g1d[S0 * 33 + j];
            a0[0] = fmaf(g, f0, a0[0]);
            a0[1] = fmaf(g, f1, a0[1]);
            a0[2] = fmaf(g, f2, a0[2]);
            a0[3] = fmaf(g, f3, a0[3]);
            a0[4] = fmaf(g, f4, a0[4]);
        }
        if (j >= 16 - R1 && j <= 16 + R1) {
            float g = g_g1d[S1 * 33 + j];
            a1[0] = fmaf(g, f0, a1[0]);
            a1[1] = fmaf(g, f1, a1[1]);
            a1[2] = fmaf(g, f2, a1[2]);
            a1[3] = fmaf(g, f3, a1[3]);
            a1[4] = fmaf(g, f4, a1[4]);
        }
        if (C == 1) {
            float g = g_g1d[S2 * 33 + j];
            a2[0] = fmaf(g, f0, a2[0]);
            a2[1] = fmaf(g, f1, a2[1]);
            a2[2] = fmaf(g, f2, a2[2]);
            a2[3] = fmaf(g, f3, a2[3]);
            a2[4] = fmaf(g, f4, a2[4]);
        }
    }

#pragma unroll
    for (int f = 0; f < 5; f++)
        g_scr[obase + (size_t)(P0 + f) * SCR_PLANE] = a0[f];
#pragma unroll
    for (int f = 0; f < 5; f++)
        g_scr[obase + (size_t)(P1 + f) * SCR_PLANE] = a1[f];
    if (C == 1) {
#pragma unroll
        for (int f = 0; f < 5; f++)
            g_scr[obase + (size_t)(P2 + f) * SCR_PLANE] = a2[f];
    }
    g_scr[obase + (size_t)(35 + C) * SCR_PLANE] = aL;
}

__global__ __launch_bounds__(256) void hconv(const float* __restrict__ x,
                                             const float* __restrict__ y) {
    __shared__ float sf[6 * 288];
    int tid = threadIdx.x;
    int cbase = blockIdx.x * 256;
    int row = blockIdx.y;
    int bc = blockIdx.z;        // b*3 + c
    int b = bc / 3, c = bc % 3;

    const float* xr = x + ((size_t)bc * 512 + row) * 512;
    const float* yr = y + ((size_t)bc * 512 + row) * 512;

    for (int idx = tid; idx < 288; idx += 256) {
        int col = cbase - 16 + idx;
        float xd = 0.0f, yd = 0.0f;
        if (col >= 0 && col < 512) {
            xd = fmaf(xr[col], 0.5f, 0.5f);
            yd = fmaf(yr[col], 0.5f, 0.5f);
        }
        sf[0 * 288 + idx] = xd;
        sf[1 * 288 + idx] = yd;
        sf[2 * 288 + idx] = xd * xd;
        sf[3 * 288 + idx] = yd * yd;
        sf[4 * 288 + idx] = xd * yd;
        sf[5 * 288 + idx] = fabsf(xd - yd);
    }
    __syncthreads();

    size_t obase = (size_t)b * PLANES_PER_B * SCR_PLANE + (size_t)row * 512 + cbase + tid;
    if (c == 0)      hwork<0>(sf, tid, obase);
    else if (c == 1) hwork<1>(sf, tid, obase);
    else             hwork<2>(sf, tid, obase);

    // raw |x-y| partial (each output pixel counted exactly once)
    float l1v = sf[5 * 288 + tid + 16];
    float bs = blockReduce256(l1v);
    if (tid == 0) g_partL1[(bc * 512 + row) * 2 + blockIdx.x] = bs;
}

// ---------------------------------------------------------------------------
// Vertical pass: tile = 32 cols x 64 rows, 256 threads (32x8), 8 rows/thread.
__device__ __forceinline__ void load_slab(float* slab, const float* __restrict__ plane,
                                          int row0, int col0, int tid) {
#pragma unroll
    for (int k = 0; k < 12; k++) {
        int idx = tid + k * 256;           // 96*32 = 3072 = 12*256
        int r = idx >> 5, c = idx & 31;
        int gr = row0 + r;
        float v = 0.0f;
        if (gr >= 0 && gr < 512) v = plane[(size_t)gr * 512 + col0 + c];
        slab[idx] = v;
    }
}

template <int RAD>
__device__ __forceinline__ void vconv8(const float* __restrict__ gk, const float* slab,
                                       int ty, int tx, float a[8]) {
    float gv[33];
#pragma unroll
    for (int j = 16 - RAD; j <= 16 + RAD; j++) gv[j] = __ldg(gk + j);
#pragma unroll
    for (int i = 0; i < 8; i++) a[i] = 0.0f;
    const float* sp = slab + ty * 8 * 32 + tx;
#pragma unroll
    for (int jr = 16 - RAD; jr <= 23 + RAD; jr++) {
        float v = sp[jr * 32];
#pragma unroll
        for (int i = 0; i < 8; i++) {
            int j = jr - i;
            if (j >= 16 - RAD && j <= 16 + RAD) a[i] = fmaf(gv[j], v, a[i]);
        }
    }
}

template <int RAD>
__device__ __forceinline__ void do_combo(int b, int pb, int s, int row0, int col0,
                                         int tid, int ty, int tx, float* slab,
                                         float prod[8], int mult, bool lm) {
    float acc[5][8];
#pragma unroll
    for (int f = 0; f < 5; f++) {
        __syncthreads();
        load_slab(slab, g_scr + (size_t)(b * PLANES_PER_B + pb + f) * SCR_PLANE,
                  row0, col0, tid);
        __syncthreads();
        vconv8<RAD>(g_g1d + s * 33, slab, ty, tx, acc[f]);
    }
#pragma unroll
    for (int i = 0; i < 8; i++) {
        float mux = acc[0][i], muy = acc[1][i];
        float mux2 = mux * mux, muy2 = muy * muy, muxy = mux * muy;
        float sxx = acc[2][i] - mux2;
        float syy = acc[3][i] - muy2;
        float sxy = acc[4][i] - muxy;
        float cs = (2.0f * sxy + C2c) / (sxx + syy + C2c);
        float m = cs;
        if (mult >= 2) m *= cs;
        if (mult >= 3) m *= cs;
        if (lm) {
            float l = (2.0f * muxy + C1c) / (mux2 + muy2 + C1c);
            m *= l * l * l;
        }
        prod[i] *= m;
    }
}

__global__ __launch_bounds__(256) void vkern() {
    __shared__ float slab[96 * 32];
    int tid = threadIdx.x;
    int tx = tid & 31, ty = tid >> 5;
    int col0 = blockIdx.x * 32;            // 16 col tiles
    int row0 = blockIdx.y * 64 - 16;       // 8 row tiles
    int b = blockIdx.z;

    float prod[8], l1s[8];
#pragma unroll
    for (int i = 0; i < 8; i++) { prod[i] = 1.0f; l1s[i] = 0.0f; }

    // combos: (plane base, sigma, radius, multiplicity, has lM)
    do_combo<3>(b, 0, 0, row0, col0, tid, ty, tx, slab, prod, 3, false);   // (c0, s0.5)^3
    do_combo<6>(b, 5, 1, row0, col0, tid, ty, tx, slab, prod, 2, false);   // (c0, s1)^2
    do_combo<6>(b, 10, 1, row0, col0, tid, ty, tx, slab, prod, 1, false);  // (c1, s1)
    do_combo<11>(b, 15, 2, row0, col0, tid, ty, tx, slab, prod, 3, false); // (c1, s2)^3
    do_combo<16>(b, 20, 3, row0, col0, tid, ty, tx, slab, prod, 1, false); // (c1, s4)
    do_combo<16>(b, 25, 3, row0, col0, tid, ty, tx, slab, prod, 2, false); // (c2, s4)^2
    do_combo<16>(b, 30, 4, row0, col0, tid, ty, tx, slab, prod, 3, true);  // (c2, s8)^3 * l^3

    // gaussian L1 planes (35..37), sigma index 4
    for (int p = 0; p < 3; p++) {
        __syncthreads();
        load_slab(slab, g_scr + (size_t)(b * PLANES_PER_B + 35 + p) * SCR_PLANE,
                  row0, col0, tid);
        __syncthreads();
        float a[8];
        vconv8<16>(g_g1d + 4 * 33, slab, ty, tx, a);
#pragma unroll
        for (int i = 0; i < 8; i++) l1s[i] += a[i];
    }

    float tsum = 0.0f;
#pragma unroll
    for (int i = 0; i < 8; i++) {
        float ms = 1.0f - prod[i];
        float gl1 = l1s[i] * (1.0f / 3.0f);
        float mix = 200.0f * (0.025f * ms + 0.975f * gl1);
        tsum += mix;
    }
    float bs = blockReduce256(tsum);
    if (tid == 0) g_partLoss[(b * 8 + blockIdx.y) * 16 + blockIdx.x] = bs;
}

// ---------------------------------------------------------------------------
__global__ void mseK(const float* __restrict__ d, int n) {
    int tid = threadIdx.x;
    float s = 0.0f;
    for (int i = tid; i < n; i += 256) {
        float v = d[i] - 1.0f;
        s = fmaf(v, v, s);
    }
    float bs = blockReduce256(s);
    if (tid == 0) g_mse[0] = bs;
}

__global__ void finalK(float* out, int ndisc) {
    int tid = threadIdx.x;
    double s1 = 0.0, s2 = 0.0;
    for (int i = tid; i < 1024; i += 256) s1 += (double)g_partLoss[i];
    for (int i = tid; i < 24576; i += 256) s2 += (double)g_partL1[i];
    __shared__ double r1[256], r2[256];
    r1[tid] = s1;
    r2[tid] = s2;
    __syncthreads();
    for (int s = 128; s > 0; s >>= 1) {
        if (tid < s) { r1[tid] += r1[tid + s]; r2[tid] += r2[tid + s]; }
        __syncthreads();
    }
    if (tid == 0) {
        double loss_mix_mean = r1[0] / 2097152.0;            // 8*512*512
        double l1_mean = r2[0] / 6291456.0;                  // 8*3*512*512
        double mse_mean = (double)g_mse[0] / (double)ndisc;
        out[0] = (float)((loss_mix_mean + 100.0 * l1_mean + mse_mean) * 0.5);
    }
}

// ---------------------------------------------------------------------------
extern "C" void kernel_launch(void* const* d_in, const int* in_sizes, int n_in,
                              void* d_out, int out_size) {
    const float* x = (const float*)d_in[0];
    const float* y = (const float*)d_in[1];
    const float* disc = (const float*)d_in[2];
    const float* gm = (const float*)d_in[3];
    int ndisc = in_sizes[2];

    initCoefs<<<1, 192>>>(gm);
    hconv<<<dim3(2, 512, 24), 256>>>(x, y);
    vkern<<<dim3(16, 8, 8), 256>>>();
    mseK<<<1, 256>>>(disc, ndisc);
    finalK<<<1, 256>>>((float*)d_out, ndisc);
}

// round 2
// speedup vs baseline: 2.2084x; 2.2084x over previous
#include <cuda_runtime.h>
#include <math.h>

// ---------------------------------------------------------------------------
// MS-SSIM + L1 loss — fully fused separable-Gaussian tile kernel.
//
// initCoefs : extract 5 x 33 1-D Gaussian kernels from g_masks diagonal.
// fusedK    : per 64x64 output tile: load 96x96 x/y slab (denormalized) to
//             smem, then for each (channel, sigma) combo do
//             horizontal 1-D conv (8-output register-blocked) -> smem tmp,
//             vertical 1-D conv (8-output register-blocked) -> registers,
//             SSIM pointwise, product across combos, block-reduce partials.
//             No DRAM scratch at all. Raw |x-y| summed during slab load.
// finalK    : disc MSE + deterministic combine -> scalar.
//
// Combos (channel, sigma-index, radius, multiplicity in PIcs, lM?):
//   c0: (s0,r3)x3, (s1,r6)x2
//   c1: (s1,r6)x1, (s2,r11)x3, (s3,r16)x1
//   c2: (s3,r16)x2, (s4,r16)x3 + l^3
// gaussian L1: sigma s4 (=8), all channels, mean over channels.
// Tap truncation radii {3,6,11,16,16}: dropped mass <= 3e-8.
// ---------------------------------------------------------------------------

#define W2 97      // x/y slab row stride (97 mod 32 == 1 -> conflict-free)
#define WT 65      // tmp row stride     (65 mod 32 == 1 -> conflict-free)
#define SMEM_FLOATS (2 * 96 * W2 + 2 * 96 * WT)   // 31104 floats = 124416 B

__device__ float g_g1d[5 * 33];
__device__ float g_partLoss[512];
__device__ float g_partL1[512];

__global__ void initCoefs(const float* __restrict__ gm) {
    int t = threadIdx.x;
    if (t < 165) {
        int s = t / 33, i = t % 33;
        // 2D mask = outer(g, g); diag[i] = g[i]^2, g >= 0.
        g_g1d[t] = sqrtf(fmaxf(gm[(3 * s) * 1089 + i * 34], 0.0f));
    }
}

// ---------------------------------------------------------------------------
// Horizontal pass: 768 slots = 96 rows x 8 col-groups (8 cols each).
// MODE 0: (x, x^2) -> t0,t1   MODE 1: (y, y^2) -> t0,t1
// MODE 2: (x*y)    -> t0      MODE 3: |x-y|    -> t0
template <int R, int MODE>
__device__ __forceinline__ void hpass(const float* __restrict__ gv,
                                      const float* sx, const float* sy,
                                      float* t0, float* t1, int tid) {
    for (int idx = tid; idx < 768; idx += 512) {
        int r = idx % 96;       // consecutive lanes -> consecutive rows: conflict-free
        int g = idx / 96;
        int base = r * W2 + g * 8 + 16 - R;
        float a0[8], a1[8];
#pragma unroll
        for (int i = 0; i < 8; i++) { a0[i] = 0.0f; a1[i] = 0.0f; }
#pragma unroll
        for (int j = 0; j < 2 * R + 8; j++) {
            float va, vb = 0.0f;
            if (MODE == 0)      { va = sx[base + j]; vb = va * va; }
            else if (MODE == 1) { va = sy[base + j]; vb = va * va; }
            else if (MODE == 2) { va = sx[base + j] * sy[base + j]; }
            else                { va = fabsf(sx[base + j] - sy[base + j]); }
#pragma unroll
            for (int i = 0; i < 8; i++) {
                int k = j - i;
                if (k >= 0 && k <= 2 * R) {
                    a0[i] = fmaf(gv[k], va, a0[i]);
                    if (MODE <= 1) a1[i] = fmaf(gv[k], vb, a1[i]);
                }
            }
        }
        int ob = r * WT + g * 8;
#pragma unroll
        for (int i = 0; i < 8; i++) {
            t0[ob + i] = a0[i];
            if (MODE <= 1) t1[ob + i] = a1[i];
        }
    }
}

// Vertical pass: 512 threads = 64 cols x 8 row-groups (8 rows each).
template <int R, int NF>
__device__ __forceinline__ void vpass(const float* __restrict__ gv,
                                      const float* t0, const float* t1,
                                      int tx, int ty, float* o0, float* o1) {
    float a0[8], a1[8];
#pragma unroll
    for (int i = 0; i < 8; i++) { a0[i] = 0.0f; a1[i] = 0.0f; }
    const float* p0 = t0 + (ty * 8 + 16 - R) * WT + tx;
    const float* p1 = t1 + (ty * 8 + 16 - R) * WT + tx;
#pragma unroll
    for (int j = 0; j < 2 * R + 8; j++) {
        float v0 = p0[j * WT];
        float v1 = (NF == 2) ? p1[j * WT] : 0.0f;
#pragma unroll
        for (int i = 0; i < 8; i++) {
            int k = j - i;
            if (k >= 0 && k <= 2 * R) {
                a0[i] = fmaf(gv[k], v0, a0[i]);
                if (NF == 2) a1[i] = fmaf(gv[k], v1, a1[i]);
            }
        }
    }
#pragma unroll
    for (int i = 0; i < 8; i++) { o0[i] = a0[i]; if (NF == 2) o1[i] = a1[i]; }
}

// One (channel, sigma) SSIM combo: 3 h+v subpasses, then pointwise into prod.
template <int R>
__device__ __forceinline__ void combo(int sIdx, int mult, bool lm,
                                      const float* sx, const float* sy,
                                      float* t0, float* t1,
                                      int tid, int tx, int ty, float* prod) {
    float gv[2 * R + 1];
#pragma unroll
    for (int j = 0; j < 2 * R + 1; j++)
        gv[j] = __ldg(&g_g1d[sIdx * 33 + 16 - R + j]);

    float mux[8], ex2[8], muy[8], ey2[8], exy[8];

    hpass<R, 0>(gv, sx, sy, t0, t1, tid);
    __syncthreads();
    vpass<R, 2>(gv, t0, t1, tx, ty, mux, ex2);
    __syncthreads();
    hpass<R, 1>(gv, sx, sy, t0, t1, tid);
    __syncthreads();
    vpass<R, 2>(gv, t0, t1, tx, ty, muy, ey2);
    __syncthreads();
    hpass<R, 2>(gv, sx, sy, t0, t1, tid);
    __syncthreads();
    vpass<R, 1>(gv, t0, t0, tx, ty, exy, (float*)0);
    __syncthreads();

#pragma unroll
    for (int i = 0; i < 8; i++) {
        float m2x = mux[i] * mux[i];
        float m2y = muy[i] * muy[i];
        float mxy = mux[i] * muy[i];
        float sxx = ex2[i] - m2x;
        float syy = ey2[i] - m2y;
        float sxyv = exy[i] - mxy;
        float cs = (2.0f * sxyv + 9.0e-4f) / (sxx + syy + 9.0e-4f);
        float m = cs;
        if (mult >= 2) m *= cs;
        if (mult >= 3) m *= cs;
        if (lm) {
            float l = (2.0f * mxy + 1.0e-4f) / (m2x + m2y + 1.0e-4f);
            m *= l * l * l;
        }
        prod[i] *= m;
    }
}

// Gaussian L1 (sigma = 8, radius 16) for the current channel.
__device__ __forceinline__ void l1pass(const float* sx, const float* sy,
                                       float* t0, int tid, int tx, int ty,
                                       float* l1s) {
    float gv[33];
#pragma unroll
    for (int j = 0; j < 33; j++) gv[j] = __ldg(&g_g1d[4 * 33 + j]);
    hpass<16, 3>(gv, sx, sy, t0, t0, tid);
    __syncthreads();
    float a[8];
    vpass<16, 1>(gv, t0, t0, tx, ty, a, (float*)0);
    __syncthreads();
#pragma unroll
    for (int i = 0; i < 8; i++) l1s[i] += a[i];
}

// ---------------------------------------------------------------------------
__global__ __launch_bounds__(512) void fusedK(const float* __restrict__ x,
                                              const float* __restrict__ y) {
    extern __shared__ float smem[];
    float* sx = smem;                 // 96 x W2
    float* sy = sx + 96 * W2;
    float* t0 = sy + 96 * W2;         // 96 x WT
    float* t1 = t0 + 96 * WT;

    int tid = threadIdx.x;
    int tx = tid & 63, ty = tid >> 6;
    int col0 = blockIdx.x * 64, row0 = blockIdx.y * 64, b = blockIdx.z;

    float prod[8], l1s[8];
#pragma unroll
    for (int i = 0; i < 8; i++) { prod[i] = 1.0f; l1s[i] = 0.0f; }
    float rawL1 = 0.0f;

    for (int c = 0; c < 3; c++) {
        const float* xp = x + (size_t)(b * 3 + c) * 262144;
        const float* yp = y + (size_t)(b * 3 + c) * 262144;
        __syncthreads();   // previous channel's smem reads complete
        for (int idx = tid; idx < 96 * 96; idx += 512) {
            int rr = idx / 96, cc = idx - rr * 96;
            int gr = row0 - 16 + rr, gc = col0 - 16 + cc;
            float xv = 0.0f, yv = 0.0f;
            if (gr >= 0 && gr < 512 && gc >= 0 && gc < 512) {
                xv = fmaf(xp[gr * 512 + gc], 0.5f, 0.5f);
                yv = fmaf(yp[gr * 512 + gc], 0.5f, 0.5f);
            }
            sx[rr * W2 + cc] = xv;
            sy[rr * W2 + cc] = yv;
            if (rr >= 16 && rr < 80 && cc >= 16 && cc < 80)
                rawL1 += fabsf(xv - yv);   // each core pixel counted once
        }
        __syncthreads();

        if (c == 0) {
            combo<3>(0, 3, false, sx, sy, t0, t1, tid, tx, ty, prod);
            combo<6>(1, 2, false, sx, sy, t0, t1, tid, tx, ty, prod);
        } else if (c == 1) {
            combo<6>(1, 1, false, sx, sy, t0, t1, tid, tx, ty, prod);
            combo<11>(2, 3, false, sx, sy, t0, t1, tid, tx, ty, prod);
            combo<16>(3, 1, false, sx, sy, t0, t1, tid, tx, ty, prod);
        } else {
            combo<16>(3, 2, false, sx, sy, t0, t1, tid, tx, ty, prod);
            combo<16>(4, 3, true, sx, sy, t0, t1, tid, tx, ty, prod);
        }
        l1pass(sx, sy, t0, tid, tx, ty, l1s);
    }

    float tsum = 0.0f;
#pragma unroll
    for (int i = 0; i < 8; i++) {
        float ms = 1.0f - prod[i];
        float mix = 200.0f * (0.025f * ms + 0.975f * (l1s[i] * (1.0f / 3.0f)));
        tsum += mix;
    }

    // Block reduction (reuse t0 region; all smem compute is done).
    __syncthreads();
    float* r1 = t0;
    float* r2 = t0 + 512;
    r1[tid] = tsum;
    r2[tid] = rawL1;
    __syncthreads();
    for (int s = 256; s > 0; s >>= 1) {
        if (tid < s) { r1[tid] += r1[tid + s]; r2[tid] += r2[tid + s]; }
        __syncthreads();
    }
    if (tid == 0) {
        int bid = (blockIdx.z * 8 + blockIdx.y) * 8 + blockIdx.x;
        g_partLoss[bid] = r1[0];
        g_partL1[bid] = r2[0];
    }
}

// ---------------------------------------------------------------------------
__global__ void finalK(float* out, const float* __restrict__ disc, int ndisc) {
    int tid = threadIdx.x;
    float ms = 0.0f;
    for (int i = tid; i < ndisc; i += 256) {
        float v = disc[i] - 1.0f;
        ms = fmaf(v, v, ms);
    }
    double s1 = 0.0, s2 = 0.0;
    for (int i = tid; i < 512; i += 256) {
        s1 += (double)g_partLoss[i];
        s2 += (double)g_partL1[i];
    }
    __shared__ double r1[256], r2[256];
    __shared__ float r3[256];
    r1[tid] = s1; r2[tid] = s2; r3[tid] = ms;
    __syncthreads();
    for (int s = 128; s > 0; s >>= 1) {
        if (tid < s) {
            r1[tid] += r1[tid + s];
            r2[tid] += r2[tid + s];
            r3[tid] += r3[tid + s];
        }
        __syncthreads();
    }
    if (tid == 0) {
        double lossMixMean = r1[0] / 2097152.0;     // 8*512*512
        double l1Mean = r2[0] / 6291456.0;          // 8*3*512*512
        double mseMean = (double)r3[0] / (double)ndisc;
        out[0] = (float)((lossMixMean + 100.0 * l1Mean + mseMean) * 0.5);
    }
}

// ---------------------------------------------------------------------------
extern "C" void kernel_launch(void* const* d_in, const int* in_sizes, int n_in,
                              void* d_out, int out_size) {
    const float* x = (const float*)d_in[0];
    const float* y = (const float*)d_in[1];
    const float* disc = (const float*)d_in[2];
    const float* gm = (const float*)d_in[3];
    int ndisc = in_sizes[2];

    cudaFuncSetAttribute(fusedK, cudaFuncAttributeMaxDynamicSharedMemorySize,
                         SMEM_FLOATS * (int)sizeof(float));
    initCoefs<<<1, 192>>>(gm);
    fusedK<<<dim3(8, 8, 8), 512, SMEM_FLOATS * sizeof(float)>>>(x, y);
    finalK<<<1, 256>>>((float*)d_out, disc, ndisc);
}

// round 4
// speedup vs baseline: 2.6313x; 1.1915x over previous
#include <cuda_runtime.h>
#include <math.h>

// ---------------------------------------------------------------------------
// MS-SSIM + L1 loss — fused separable-Gaussian tile kernel, FFMA2-packed.
//
// Per 64x64 output tile: load 96x96 x/y slab (denormalized) to smem; for each
// (channel, sigma) combo:
//   hpassP/vpassP : packed (v, v^2) 1-D convs via fma.rn.f32x2 -> mu, E[v^2]
//   carrier combo : packed (x*y, |x-y|) dual conv (per-lane coefs sigma / s4)
//                   -> E[xy] and gaussian-L1 in one pass
//   other combos  : scalar xy conv
// SSIM pointwise, product across combos, block reduction. No DRAM scratch.
//
// Combos: c0: (s0,r3)x3, (s1,r6)x2[carrier]
//         c1: (s1,r6)x1, (s2,r11)x3, (s3,r16)x1[carrier]
//         c2: (s3,r16)x2, (s4,r16)x3 + l^3 [carrier]
// ---------------------------------------------------------------------------

typedef unsigned long long u64;

#define W2 97     // x/y slab row stride (floats); 97 % 32 == 1 -> conflict-free
#define WT 65     // scalar tmp row stride (floats)
#define WTU 65    // packed tmp row stride (u64)
#define SMEM_BYTES (2 * 96 * W2 * 4 + 96 * WTU * 8)   // 74496 + 49920 = 124416

__device__ float g_g1d[5 * 33];
__device__ float g_partLoss[512];
__device__ float g_partL1[512];

__global__ void initCoefs(const float* __restrict__ gm) {
    int t = threadIdx.x;
    if (t < 165) {
        int s = t / 33, i = t % 33;
        g_g1d[t] = sqrtf(fmaxf(gm[(3 * s) * 1089 + i * 34], 0.0f));
    }
}

// ---------------------------------------------------------------------------
__device__ __forceinline__ u64 pk2(float lo, float hi) {
    u64 r; asm("mov.b64 %0, {%1, %2};" : "=l"(r) : "f"(lo), "f"(hi)); return r;
}
__device__ __forceinline__ void upk2(u64 v, float& lo, float& hi) {
    asm("mov.b64 {%0, %1}, %2;" : "=f"(lo), "=f"(hi) : "l"(v));
}
__device__ __forceinline__ u64 ffma2(u64 a, u64 b, u64 c) {
    u64 d; asm("fma.rn.f32x2 %0, %1, %2, %3;" : "=l"(d) : "l"(a), "l"(b), "l"(c));
    return d;
}

// ---------------------------------------------------------------------------
// Packed (v, v^2) horizontal conv. 768 slots = 96 rows x 8 col-groups.
template <int R>
__device__ __forceinline__ void hpassP(const float* __restrict__ s, u64* t2,
                                       const float* __restrict__ g1, int tid) {
    for (int idx = tid; idx < 768; idx += 512) {
        int r = idx % 96, gq = idx / 96;
        const float* p = s + r * W2 + gq * 8 + (16 - R);
        u64 acc[8], w[8];
#pragma unroll
        for (int j = 0; j < 8; j++) { float f = p[j]; w[j] = pk2(f, f * f); }
#pragma unroll
        for (int i = 0; i < 8; i++) acc[i] = 0ULL;
#pragma unroll
        for (int k = 0; k <= 2 * R; k++) {
            float gk = __ldg(g1 + k);
            u64 c2 = pk2(gk, gk);
#pragma unroll
            for (int i = 0; i < 8; i++) acc[i] = ffma2(c2, w[(k + i) & 7], acc[i]);
            if (k < 2 * R) { float f = p[k + 8]; w[k & 7] = pk2(f, f * f); }
        }
        u64* ob = t2 + r * WTU + gq * 8;
#pragma unroll
        for (int i = 0; i < 8; i++) ob[i] = acc[i];
    }
}

// Packed vertical conv (coefs equal per lane). 512 threads = 64 cols x 8 groups.
template <int R>
__device__ __forceinline__ void vpassP(const u64* t2, const float* __restrict__ g1,
                                       int tx, int ty, u64 out[8]) {
    const u64* p = t2 + (ty * 8 + 16 - R) * WTU + tx;
    u64 acc[8], w[8];
#pragma unroll
    for (int j = 0; j < 8; j++) w[j] = p[j * WTU];
#pragma unroll
    for (int i = 0; i < 8; i++) acc[i] = 0ULL;
#pragma unroll
    for (int k = 0; k <= 2 * R; k++) {
        float gk = __ldg(g1 + k);
        u64 c2 = pk2(gk, gk);
#pragma unroll
        for (int i = 0; i < 8; i++) acc[i] = ffma2(c2, w[(k + i) & 7], acc[i]);
        if (k < 2 * R) w[k & 7] = p[(k + 8) * WTU];
    }
#pragma unroll
    for (int i = 0; i < 8; i++) out[i] = acc[i];
}

// Dual (x*y, |x-y|) horizontal conv at full 33-tap window; per-lane coefs.
__device__ __forceinline__ void hpassXY(const float* sx, const float* sy, u64* t2,
                                        const float* __restrict__ gA,
                                        const float* __restrict__ gB, int tid) {
    for (int idx = tid; idx < 768; idx += 512) {
        int r = idx % 96, gq = idx / 96;
        const float* px = sx + r * W2 + gq * 8;
        const float* py = sy + r * W2 + gq * 8;
        u64 acc[8], w[8];
#pragma unroll
        for (int j = 0; j < 8; j++) {
            float xv = px[j], yv = py[j];
            w[j] = pk2(xv * yv, fabsf(xv - yv));
        }
#pragma unroll
        for (int i = 0; i < 8; i++) acc[i] = 0ULL;
#pragma unroll
        for (int k = 0; k <= 32; k++) {
            u64 c2 = pk2(__ldg(gA + k), __ldg(gB + k));
#pragma unroll
            for (int i = 0; i < 8; i++) acc[i] = ffma2(c2, w[(k + i) & 7], acc[i]);
            if (k < 32) {
                float xv = px[k + 8], yv = py[k + 8];
                w[k & 7] = pk2(xv * yv, fabsf(xv - yv));
            }
        }
        u64* ob = t2 + r * WTU + gq * 8;
#pragma unroll
        for (int i = 0; i < 8; i++) ob[i] = acc[i];
    }
}

__device__ __forceinline__ void vpassXY(const u64* t2,
                                        const float* __restrict__ gA,
                                        const float* __restrict__ gB,
                                        int tx, int ty, u64 out[8]) {
    const u64* p = t2 + ty * 8 * WTU + tx;
    u64 acc[8], w[8];
#pragma unroll
    for (int j = 0; j < 8; j++) w[j] = p[j * WTU];
#pragma unroll
    for (int i = 0; i < 8; i++) acc[i] = 0ULL;
#pragma unroll
    for (int k = 0; k <= 32; k++) {
        u64 c2 = pk2(__ldg(gA + k), __ldg(gB + k));
#pragma unroll
        for (int i = 0; i < 8; i++) acc[i] = ffma2(c2, w[(k + i) & 7], acc[i]);
        if (k < 32) w[k & 7] = p[(k + 8) * WTU];
    }
#pragma unroll
    for (int i = 0; i < 8; i++) out[i] = acc[i];
}

// Scalar xy conv (non-carrier combos).
template <int R>
__device__ __forceinline__ void hpassS(const float* sx, const float* sy, float* t0,
                                       const float* __restrict__ g1, int tid) {
    for (int idx = tid; idx < 768; idx += 512) {
        int r = idx % 96, gq = idx / 96;
        const float* px = sx + r * W2 + gq * 8 + (16 - R);
        const float* py = sy + r * W2 + gq * 8 + (16 - R);
        float acc[8], w[8];
#pragma unroll
        for (int j = 0; j < 8; j++) w[j] = px[j] * py[j];
#pragma unroll
        for (int i = 0; i < 8; i++) acc[i] = 0.0f;
#pragma unroll
        for (int k = 0; k <= 2 * R; k++) {
            float gk = __ldg(g1 + k);
#pragma unroll
            for (int i = 0; i < 8; i++) acc[i] = fmaf(gk, w[(k + i) & 7], acc[i]);
            if (k < 2 * R) w[k & 7] = px[k + 8] * py[k + 8];
        }
        float* ob = t0 + r * WT + gq * 8;
#pragma unroll
        for (int i = 0; i < 8; i++) ob[i] = acc[i];
    }
}

template <int R>
__device__ __forceinline__ void vpassS(const float* t0, const float* __restrict__ g1,
                                       int tx, int ty, float out[8]) {
    const float* p = t0 + (ty * 8 + 16 - R) * WT + tx;
    float acc[8], w[8];
#pragma unroll
    for (int j = 0; j < 8; j++) w[j] = p[j * WT];
#pragma unroll
    for (int i = 0; i < 8; i++) acc[i] = 0.0f;
#pragma unroll
    for (int k = 0; k <= 2 * R; k++) {
        float gk = __ldg(g1 + k);
#pragma unroll
        for (int i = 0; i < 8; i++) acc[i] = fmaf(gk, w[(k + i) & 7], acc[i]);
        if (k < 2 * R) w[k & 7] = p[(k + 8) * WT];
    }
#pragma unroll
    for (int i = 0; i < 8; i++) out[i] = acc[i];
}

// ---------------------------------------------------------------------------
template <int R, bool CARRIER>
__device__ __forceinline__ void comboP(int sIdx, int mult, bool lm,
                                       const float* sx, const float* sy, u64* t2,
                                       int tid, int tx, int ty,
                                       float prod[8], float l1s[8]) {
    const float* g1 = g_g1d + sIdx * 33 + (16 - R);
    u64 o1[8], o2[8];
    float exy[8];

    hpassP<R>(sx, t2, g1, tid);
    __syncthreads();
    vpassP<R>(t2, g1, tx, ty, o1);
    __syncthreads();
    hpassP<R>(sy, t2, g1, tid);
    __syncthreads();
    vpassP<R>(t2, g1, tx, ty, o2);
    __syncthreads();

    if (CARRIER) {
        const float* gA = g_g1d + sIdx * 33;
        const float* gB = g_g1d + 4 * 33;
        u64 o3[8];
        hpassXY(sx, sy, t2, gA, gB, tid);
        __syncthreads();
        vpassXY(t2, gA, gB, tx, ty, o3);
        __syncthreads();
#pragma unroll
        for (int i = 0; i < 8; i++) {
            float lv;
            upk2(o3[i], exy[i], lv);
            l1s[i] += lv;
        }
    } else {
        float* t0 = (float*)t2;
        hpassS<R>(sx, sy, t0, g1, tid);
        __syncthreads();
        vpassS<R>(t0, g1, tx, ty, exy);
        __syncthreads();
    }

#pragma unroll
    for (int i = 0; i < 8; i++) {
        float mux, ex2, muy, ey2;
        upk2(o1[i], mux, ex2);
        upk2(o2[i], muy, ey2);
        float m2x = mux * mux, m2y = muy * muy, mxy = mux * muy;
        float sxx = ex2 - m2x, syy = ey2 - m2y, sxyv = exy[i] - mxy;
        float cs = __fdividef(2.0f * sxyv + 9.0e-4f, sxx + syy + 9.0e-4f);
        float m = cs;
        if (mult >= 2) m *= cs;
        if (mult >= 3) m *= cs;
        if (lm) {
            float l = __fdividef(2.0f * mxy + 1.0e-4f, m2x + m2y + 1.0e-4f);
            m *= l * l * l;
        }
        prod[i] *= m;
    }
}

// ---------------------------------------------------------------------------
__global__ __launch_bounds__(512) void fusedK(const float* __restrict__ x,
                                              const float* __restrict__ y) {
    extern __shared__ float smem[];
    float* sx = smem;                   // 96 x W2
    float* sy = sx + 96 * W2;
    u64* t2 = (u64*)(sy + 96 * W2);     // 96 x WTU u64

    int tid = threadIdx.x;
    int tx = tid & 63, ty = tid >> 6;
    int col0 = blockIdx.x * 64, row0 = blockIdx.y * 64, b = blockIdx.z;

    float prod[8], l1s[8];
#pragma unroll
    for (int i = 0; i < 8; i++) { prod[i] = 1.0f; l1s[i] = 0.0f; }
    float rawL1 = 0.0f;

    for (int c = 0; c < 3; c++) {
        const float* xp = x + (size_t)(b * 3 + c) * 262144;
        const float* yp = y + (size_t)(b * 3 + c) * 262144;
        __syncthreads();
        for (int idx = tid; idx < 96 * 96; idx += 512) {
            int rr = idx / 96, cc = idx - rr * 96;
            int gr = row0 - 16 + rr, gc = col0 - 16 + cc;
            float xv = 0.0f, yv = 0.0f;
            if (gr >= 0 && gr < 512 && gc >= 0 && gc < 512) {
                xv = fmaf(xp[gr * 512 + gc], 0.5f, 0.5f);
                yv = fmaf(yp[gr * 512 + gc], 0.5f, 0.5f);
            }
            sx[rr * W2 + cc] = xv;
            sy[rr * W2 + cc] = yv;
            if (rr >= 16 && rr < 80 && cc >= 16 && cc < 80)
                rawL1 += fabsf(xv - yv);
        }
        __syncthreads();

        if (c == 0) {
            comboP<3, false>(0, 3, false, sx, sy, t2, tid, tx, ty, prod, l1s);
            comboP<6, true>(1, 2, false, sx, sy, t2, tid, tx, ty, prod, l1s);
        } else if (c == 1) {
            comboP<6, false>(1, 1, false, sx, sy, t2, tid, tx, ty, prod, l1s);
            comboP<11, false>(2, 3, false, sx, sy, t2, tid, tx, ty, prod, l1s);
            comboP<16, true>(3, 1, false, sx, sy, t2, tid, tx, ty, prod, l1s);
        } else {
            comboP<16, false>(3, 2, false, sx, sy, t2, tid, tx, ty, prod, l1s);
            comboP<16, true>(4, 3, true, sx, sy, t2, tid, tx, ty, prod, l1s);
        }
    }

    float tsum = 0.0f;
#pragma unroll
    for (int i = 0; i < 8; i++) {
        float ms = 1.0f - prod[i];
        float mix = 200.0f * (0.025f * ms + 0.975f * (l1s[i] * (1.0f / 3.0f)));
        tsum += mix;
    }

    __syncthreads();
    float* r1 = (float*)t2;
    float* r2 = r1 + 512;
    r1[tid] = tsum;
    r2[tid] = rawL1;
    __syncthreads();
    for (int s = 256; s > 0; s >>= 1) {
        if (tid < s) { r1[tid] += r1[tid + s]; r2[tid] += r2[tid + s]; }
        __syncthreads();
    }
    if (tid == 0) {
        int bid = (blockIdx.z * 8 + blockIdx.y) * 8 + blockIdx.x;
        g_partLoss[bid] = r1[0];
        g_partL1[bid] = r2[0];
    }
}

// ---------------------------------------------------------------------------
__global__ void finalK(float* out, const float* __restrict__ disc, int ndisc) {
    int tid = threadIdx.x;
    float ms = 0.0f;
    for (int i = tid; i < ndisc; i += 256) {
        float v = disc[i] - 1.0f;
        ms = fmaf(v, v, ms);
    }
    double s1 = 0.0, s2 = 0.0;
    for (int i = tid; i < 512; i += 256) {
        s1 += (double)g_partLoss[i];
        s2 += (double)g_partL1[i];
    }
    __shared__ double r1[256], r2[256];
    __shared__ float r3[256];
    r1[tid] = s1; r2[tid] = s2; r3[tid] = ms;
    __syncthreads();
    for (int s = 128; s > 0; s >>= 1) {
        if (tid < s) {
            r1[tid] += r1[tid + s];
            r2[tid] += r2[tid + s];
            r3[tid] += r3[tid + s];
        }
        __syncthreads();
    }
    if (tid == 0) {
        double lossMixMean = r1[0] / 2097152.0;     // 8*512*512
        double l1Mean = r2[0] / 6291456.0;          // 8*3*512*512
        double mseMean = (double)r3[0] / (double)ndisc;
        out[0] = (float)((lossMixMean + 100.0 * l1Mean + mseMean) * 0.5);
    }
}

// ---------------------------------------------------------------------------
extern "C" void kernel_launch(void* const* d_in, const int* in_sizes, int n_in,
                              void* d_out, int out_size) {
    const float* x = (const float*)d_in[0];
    const float* y = (const float*)d_in[1];
    const float* disc = (const float*)d_in[2];
    const float* gm = (const float*)d_in[3];
    int ndisc = in_sizes[2];

    cudaFuncSetAttribute(fusedK, cudaFuncAttributeMaxDynamicSharedMemorySize,
                         SMEM_BYTES);
    initCoefs<<<1, 192>>>(gm);
    fusedK<<<dim3(8, 8, 8), 512, SMEM_BYTES>>>(x, y);
    finalK<<<1, 256>>>((float*)d_out, disc, ndisc);
}